// round 16
// baseline (speedup 1.0000x reference)
#include <cuda_runtime.h>
#include <cuda_fp16.h>
#include <cstdint>

// ============================================================================
// Problem constants
// ============================================================================
#define PADV (-10000.0f)
static constexpr int BB = 512;
static constexpr int NN = 2048;
static constexpr int FF = 16;
static constexpr int HH = 128;
static constexpr int TILES2 = 32;                    // 64-row units per batch
static constexpr int NSLOTS2 = BB * TILES2;          // 16384
static constexpr int PHI_GRID = 148;
static constexpr int PHI_THREADS = 512;              // 16 warps = 2 groups x 8

// ============================================================================
// Device globals (scratch; allocation-free rule; zero-init at module load,
// re-zeroed at the tail of rho_kernel each run)
// ============================================================================
__device__ int   g_len[BB];
__device__ int   g_ticket;
__device__ int   g_nwork;
__device__ int   g_done_cnt;
__device__ int   g_work[NSLOTS2];
__device__ float g_partial[(size_t)NSLOTS2 * HH];    // 8 MB partial pooled sums

// ============================================================================
// SMEM layout (dynamic, phi kernel) — 1 CTA/SM, ~180 KB
// ============================================================================
static constexpr int W1_OFF   = 0;
static constexpr int W2_OFF   = 32768;
static constexpr int W3_OFF   = 65536;
static constexpr int W0_OFF   = 98304;    // 128 n-rows x 48B = 6144
static constexpr int GRP_OFF  = 104448;   // two group blocks follow
static constexpr int GRP_SZ   = 38912;
static constexpr int GA2_OFF  = 0;        // + 3072
static constexpr int GAP0_OFF = 3072;     // + 16384
static constexpr int GAP1_OFF = 19456;    // + 16384
static constexpr int GRED_OFF = 35840;    // + 2048
static constexpr int GSLOT_OFF= 37888;    // + 64
static constexpr int BIAS_OFF = GRP_OFF + 2 * GRP_SZ;   // 182272, 2048B
static constexpr int SMEM_TOTAL = BIAS_OFF + 2048;      // 184320

// ============================================================================
// PTX helpers (arch-generic: ldmatrix + mma.sync fp16)
// ============================================================================
__device__ __forceinline__ uint32_t smem_to_u32(const void* smem_ptr) {
    uint32_t addr;
    asm("{ .reg .u64 tmp; cvta.to.shared.u64 tmp, %1; cvt.u32.u64 %0, tmp; }"
        : "=r"(addr) : "l"(smem_ptr));
    return addr;
}

__device__ __forceinline__ void ldsm4(uint32_t (&r)[4], uint32_t addr) {
    asm volatile("ldmatrix.sync.aligned.m8n8.x4.shared.b16 {%0,%1,%2,%3}, [%4];"
        : "=r"(r[0]), "=r"(r[1]), "=r"(r[2]), "=r"(r[3]) : "r"(addr));
}

// fp32-accumulate HMMA
__device__ __forceinline__ void mma16816(float (&c)[4], const uint32_t (&a)[4],
                                         uint32_t b0, uint32_t b1) {
    asm volatile(
        "mma.sync.aligned.m16n8k16.row.col.f32.f16.f16.f32 "
        "{%0,%1,%2,%3}, {%4,%5,%6,%7}, {%8,%9}, {%0,%1,%2,%3};"
        : "+f"(c[0]), "+f"(c[1]), "+f"(c[2]), "+f"(c[3])
        : "r"(a[0]), "r"(a[1]), "r"(a[2]), "r"(a[3]), "r"(b0), "r"(b1));
}

// fp16-accumulate HMMA (rate experiment: possibly 2x fp32-accum)
__device__ __forceinline__ void mma16816h(uint32_t (&d)[2], const uint32_t (&a)[4],
                                          uint32_t b0, uint32_t b1) {
    asm volatile(
        "mma.sync.aligned.m16n8k16.row.col.f16.f16.f16.f16 "
        "{%0,%1}, {%2,%3,%4,%5}, {%6,%7}, {%0,%1};"
        : "+r"(d[0]), "+r"(d[1])
        : "r"(a[0]), "r"(a[1]), "r"(a[2]), "r"(a[3]), "r"(b0), "r"(b1));
}

__device__ __forceinline__ uint32_t pack_f16x2(float e, float o) {
    uint32_t r;
    asm("cvt.rn.satfinite.f16x2.f32 %0, %1, %2;" : "=r"(r) : "f"(o), "f"(e));
    return r;
}

// swizzled byte offset: row stride 256B, 16B-chunk XOR swizzle
__device__ __forceinline__ uint32_t mswz(int row, int k) {
    return (uint32_t)row * 256u + (((uint32_t)k * 2u) ^ (((uint32_t)row & 7u) << 4));
}

// group-scoped named barrier (ids 1,2; 256 threads each)
__device__ __forceinline__ void gbar(int id) {
    asm volatile("bar.sync %0, %1;" :: "r"(id), "r"(256) : "memory");
}

__device__ __forceinline__ bool row_is_pad(const float* xb, int row) {
    float4 v = __ldg((const float4*)(xb + (size_t)row * FF));
    return (v.x == PADV) & (v.y == PADV) & (v.z == PADV) & (v.w == PADV);
}

// ============================================================================
// Kernel: persistent phi — fused length-scan prologue + fp16 mma.sync,
// TWO independent 8-warp tile pipelines per CTA (named barriers).
// ============================================================================
__global__ void __launch_bounds__(PHI_THREADS, 1)
phi_kernel(const float* __restrict__ x,
           const float* __restrict__ w0, const float* __restrict__ b0,
           const float* __restrict__ w1, const float* __restrict__ b1,
           const float* __restrict__ w2, const float* __restrict__ b2,
           const float* __restrict__ w3, const float* __restrict__ b3) {
    extern __shared__ __align__(1024) char smem[];
    const int tid  = threadIdx.x;
    const int wid  = tid >> 5;
    const int lane = tid & 31;
    const int gid  = wid >> 3;          // pipeline group 0/1
    const int ltid = tid & 255;         // tid within group
    const int lwid = wid & 7;           // warp within group
    const int rg   = lwid >> 1;         // row-group 0..3 (16 rows each)
    const int ch   = lwid & 1;          // col-half 0..1 (64 cols each)
    const int barid = gid + 1;
    const uint32_t smem_base = smem_to_u32(smem);

    // ==== prologue: warps 0-3 compute lengths; warps 4-15 stage weights ====
    if (wid < 4) {
        const int bb = blockIdx.x * 4 + wid;
        if (bb < BB) {
            const float* xb = x + (size_t)bb * NN * FF;
            bool p1 = row_is_pad(xb, lane * 64);
            unsigned m1 = __ballot_sync(0xFFFFFFFFu, p1);
            int L;
            if (m1 == 0) L = 2048 - 64;
            else         L = (__ffs(m1) - 1 - 1) * 64;    // bit0 never set (len>=1)
            bool p2 = row_is_pad(xb, L + 1 + 2 * lane);
            unsigned m2 = __ballot_sync(0xFFFFFFFFu, p2);
            int len;
            if (m2 == 0) {
                len = L + 64;
            } else {
                int t0 = __ffs(m2) - 1;
                bool pm = row_is_pad(xb, L + 2 * t0);
                unsigned mm = __ballot_sync(0xFFFFFFFFu, pm);
                len = (mm & 1u) ? (L + 2 * t0) : (L + 2 * t0 + 1);
            }
            if (lane == 0) {
                g_len[bb] = len;
                int nt = (len + 63) >> 6;
                int base = atomicAdd(&g_nwork, nt);
                for (int t = 0; t < nt; t++) g_work[base + t] = (bb << 5) | t;
                __threadfence();
                atomicAdd(&g_done_cnt, 1);
            }
        }
        // bias staging by warps 0-3 after their (short) length scan
        if (tid < HH) {
            float* bs = (float*)(smem + BIAS_OFF);
            bs[tid]          = b0[tid];
            bs[HH + tid]     = b1[tid];
            bs[2 * HH + tid] = b2[tid];
            bs[3 * HH + tid] = b3[tid];
        }
    } else {
        const int st = tid - 128;                         // 0..383
        const float* Wg[3] = { w1, w2, w3 };
        const int    Wo[3] = { W1_OFF, W2_OFF, W3_OFF };
        for (int Li = 0; Li < 3; Li++) {
            const float* W = Wg[Li];
            for (int i = st; i < HH * HH; i += 384) {
                int k = i >> 7, n = i & 127;
                *reinterpret_cast<__half*>(smem + Wo[Li] + mswz(n, k)) = __float2half(W[i]);
            }
        }
        for (int i = st; i < FF * HH; i += 384) {
            int k = i >> 7, n = i & 127;
            *reinterpret_cast<__half*>(smem + W0_OFF + n * 48 + k * 2) = __float2half(w0[i]);
        }
    }
    __syncthreads();

    // wait for ALL lengths (any CTA may process any batch)
    if (ltid == 0) {
        while (*(volatile int*)&g_done_cnt < BB) { }
        __threadfence();
    }
    gbar(barid);
    const int nwork = g_nwork;

    const float* bias = (const float*)(smem + BIAS_OFF);
    const int GB = GRP_OFF + gid * GRP_SZ;
    int* s_slot = (int*)(smem + GB + GSLOT_OFF);
    float* red  = (float*)(smem + GB + GRED_OFF);
    const uint32_t WB[3] = { smem_base + W1_OFF, smem_base + W2_OFF, smem_base + W3_OFF };
    const uint32_t W0b = smem_base + W0_OFF;
    const uint32_t A2b = smem_base + GB + GA2_OFF;
    const uint32_t AB[2] = { smem_base + GB + GAP0_OFF, smem_base + GB + GAP1_OFF };

    // per-thread fragment coordinates (rows within the 64-row unit)
    const int ar = rg * 16 + (lane & 15);
    const int akh = (lane >> 4) << 3;
    const int bn = ch * 64 + (lane & 7) + ((lane >> 4) << 3);
    const int bk = ((lane >> 3) & 1) << 3;
    const int r0 = rg * 16 + (lane >> 2);
    const int cc0 = ch * 64 + (lane & 3) * 2;
    const int xrow = ltid >> 2, xseg = ltid & 3;

    while (true) {
        gbar(barid);
        if (ltid == 0) *s_slot = atomicAdd(&g_ticket, 1);
        gbar(barid);
        const int idx = *s_slot;
        if (idx >= nwork) break;
        const int slot = g_work[idx];
        const int b = slot >> 5, t = slot & 31;
        const int valid = min(64, g_len[b] - t * 64);
        const bool wact = (rg * 16 < valid);

        // ---- stage x unit -> A2 as fp16 (48B stride), zero invalid rows ----
        {
            float4 v = __ldg((const float4*)(x + ((size_t)b * NN + t * 64 + xrow) * FF + xseg * 4));
            uint32_t p0 = 0, p1 = 0;
            if (xrow < valid) { p0 = pack_f16x2(v.x, v.y); p1 = pack_f16x2(v.z, v.w); }
            *(uint32_t*)(smem + GB + GA2_OFF + xrow * 48 + xseg * 8)     = p0;
            *(uint32_t*)(smem + GB + GA2_OFF + xrow * 48 + xseg * 8 + 4) = p1;
        }
        gbar(barid);

        // ---- layer 0: K=16 MMA (fp32 accum, cheap) -> AP0 ----
        if (wact) {
            float c[8][4];
            #pragma unroll
            for (int nb = 0; nb < 8; nb++)
                #pragma unroll
                for (int j = 0; j < 4; j++) c[nb][j] = 0.f;
            uint32_t a[4];
            ldsm4(a, A2b + ar * 48 + akh * 2);
            #pragma unroll
            for (int p = 0; p < 4; p++) {
                uint32_t bh[4];
                ldsm4(bh, W0b + (bn + p * 16) * 48 + bk * 2);
                mma16816(c[2 * p],     a, bh[0], bh[1]);
                mma16816(c[2 * p + 1], a, bh[2], bh[3]);
            }
            const float* bl_ = bias;
            #pragma unroll
            for (int nb = 0; nb < 8; nb++) {
                int col = cc0 + nb * 8;
                float be = bl_[col], bo = bl_[col + 1];
                uint32_t p0 = pack_f16x2(fmaxf(c[nb][0] + be, 0.f), fmaxf(c[nb][1] + bo, 0.f));
                uint32_t p1 = pack_f16x2(fmaxf(c[nb][2] + be, 0.f), fmaxf(c[nb][3] + bo, 0.f));
                *(uint32_t*)(smem + GB + GAP0_OFF + mswz(r0, col))     = p0;
                *(uint32_t*)(smem + GB + GAP0_OFF + mswz(r0 + 8, col)) = p1;
            }
        }
        gbar(barid);

        // ---- layers 1..2: fp16-accum MMA (2 accumulator sets, K=64 each) ----
        #pragma unroll
        for (int L = 0; L < 2; L++) {
            const uint32_t Acur = AB[L & 1];
            const uint32_t Wb = WB[L];
            if (wact) {
                uint32_t da[8][2], db[8][2];
                #pragma unroll
                for (int nb = 0; nb < 8; nb++) {
                    da[nb][0] = 0u; da[nb][1] = 0u;
                    db[nb][0] = 0u; db[nb][1] = 0u;
                }
                #pragma unroll
                for (int kb = 0; kb < 8; kb++) {
                    uint32_t a[4];
                    ldsm4(a, Acur + mswz(ar, kb * 16 + akh));
                    #pragma unroll
                    for (int p = 0; p < 4; p++) {
                        uint32_t bh[4];
                        ldsm4(bh, Wb + mswz(bn + p * 16, kb * 16 + bk));
                        if (kb < 4) {
                            mma16816h(da[2 * p],     a, bh[0], bh[1]);
                            mma16816h(da[2 * p + 1], a, bh[2], bh[3]);
                        } else {
                            mma16816h(db[2 * p],     a, bh[0], bh[1]);
                            mma16816h(db[2 * p + 1], a, bh[2], bh[3]);
                        }
                    }
                }
                // epilogue: fp32 combine of the two fp16 sets + bias + ReLU
                const float* bl_ = bias + (L + 1) * HH;
                const uint32_t Anxt = (uint32_t)(GB + ((L & 1) ? GAP0_OFF : GAP1_OFF));
                #pragma unroll
                for (int nb = 0; nb < 8; nb++) {
                    int col = cc0 + nb * 8;
                    float be = bl_[col], bo = bl_[col + 1];
                    float2 fa0 = __half22float2(*(const __half2*)&da[nb][0]);
                    float2 fb0 = __half22float2(*(const __half2*)&db[nb][0]);
                    float2 fa1 = __half22float2(*(const __half2*)&da[nb][1]);
                    float2 fb1 = __half22float2(*(const __half2*)&db[nb][1]);
                    uint32_t p0 = pack_f16x2(fmaxf(fa0.x + fb0.x + be, 0.f),
                                             fmaxf(fa0.y + fb0.y + bo, 0.f));
                    uint32_t p1 = pack_f16x2(fmaxf(fa1.x + fb1.x + be, 0.f),
                                             fmaxf(fa1.y + fb1.y + bo, 0.f));
                    *(uint32_t*)(smem + Anxt + mswz(r0, col))     = p0;
                    *(uint32_t*)(smem + Anxt + mswz(r0 + 8, col)) = p1;
                }
            }
            gbar(barid);
        }

        // ---- layer 3 (final): fp32-accum MMA + masked column-sum pooling ----
        {
            const uint32_t Acur = AB[0];     // after L=0,1 the live buffer is AP0
            const uint32_t Wb = WB[2];
            if (wact) {
                float c[8][4];
                #pragma unroll
                for (int nb = 0; nb < 8; nb++)
                    #pragma unroll
                    for (int j = 0; j < 4; j++) c[nb][j] = 0.f;
                #pragma unroll
                for (int kb = 0; kb < 8; kb++) {
                    uint32_t a[4];
                    ldsm4(a, Acur + mswz(ar, kb * 16 + akh));
                    #pragma unroll
                    for (int p = 0; p < 4; p++) {
                        uint32_t bh[4];
                        ldsm4(bh, Wb + mswz(bn + p * 16, kb * 16 + bk));
                        mma16816(c[2 * p],     a, bh[0], bh[1]);
                        mma16816(c[2 * p + 1], a, bh[2], bh[3]);
                    }
                }
                const float* b3s = bias + 3 * HH;
                const float m0 = (r0 < valid) ? 1.f : 0.f;
                const float m1 = (r0 + 8 < valid) ? 1.f : 0.f;
                #pragma unroll
                for (int nb = 0; nb < 8; nb++) {
                    int col = cc0 + nb * 8;
                    float be = b3s[col], bo = b3s[col + 1];
                    float s0 = m0 * fmaxf(c[nb][0] + be, 0.f) + m1 * fmaxf(c[nb][2] + be, 0.f);
                    float s1 = m0 * fmaxf(c[nb][1] + bo, 0.f) + m1 * fmaxf(c[nb][3] + bo, 0.f);
                    #pragma unroll
                    for (int off = 4; off < 32; off <<= 1) {
                        s0 += __shfl_xor_sync(0xFFFFFFFFu, s0, off);
                        s1 += __shfl_xor_sync(0xFFFFFFFFu, s1, off);
                    }
                    if (lane < 4) {
                        int cc = ch * 64 + nb * 8 + lane * 2;
                        red[rg * HH + cc]     = s0;
                        red[rg * HH + cc + 1] = s1;
                    }
                }
            } else {
                if (lane < 4) {
                    #pragma unroll
                    for (int nb = 0; nb < 8; nb++) {
                        int cc = ch * 64 + nb * 8 + lane * 2;
                        red[rg * HH + cc]     = 0.f;
                        red[rg * HH + cc + 1] = 0.f;
                    }
                }
            }
            gbar(barid);
            if (ltid < HH) {
                float s = red[ltid] + red[HH + ltid] + red[2 * HH + ltid] + red[3 * HH + ltid];
                g_partial[(size_t)slot * HH + ltid] = s;
            }
        }
    }
}

// ============================================================================
// Kernel: rho (fp32 SIMT) — 1 batch/block, K split across 2 thread-halves;
// resets scheduler counters at the tail.
// ============================================================================
__global__ void __launch_bounds__(256)
rho_kernel(const float* __restrict__ w0, const float* __restrict__ b0,
           const float* __restrict__ w1, const float* __restrict__ b1,
           const float* __restrict__ w2, const float* __restrict__ b2,
           const float* __restrict__ w3, const float* __restrict__ b3,
           float* __restrict__ out) {
    __shared__ float s_in[HH];
    __shared__ float s_part[2][HH];
    const int b = blockIdx.x;
    const int j = threadIdx.x & 127;
    const int h = threadIdx.x >> 7;

    {
        const int nt = (g_len[b] + 63) >> 6;
        float acc = 0.f;
        for (int t = h; t < nt; t += 2)
            acc += g_partial[((size_t)b * TILES2 + t) * HH + j];
        s_part[h][j] = acc;
    }
    __syncthreads();
    if (h == 0) s_in[j] = s_part[0][j] + s_part[1][j];
    __syncthreads();

    const float* Ws[3] = { w0, w1, w2 };
    const float* Bs[3] = { b0, b1, b2 };
    #pragma unroll
    for (int L = 0; L < 3; L++) {
        const float* W = Ws[L] + (size_t)h * 64 * HH;
        float p = 0.f;
        #pragma unroll 16
        for (int kk = 0; kk < 64; kk++)
            p = fmaf(s_in[h * 64 + kk], __ldg(W + kk * HH + j), p);
        s_part[h][j] = p;
        __syncthreads();
        if (h == 0) s_in[j] = fmaxf(s_part[0][j] + s_part[1][j] + Bs[L][j], 0.f);
        __syncthreads();
    }

    if (h == 0) s_part[0][j] = s_in[j] * __ldg(w3 + j);
    __syncthreads();
    if (threadIdx.x < 32) {
        const int lane = threadIdx.x;
        float s = s_part[0][lane] + s_part[0][lane + 32]
                + s_part[0][lane + 64] + s_part[0][lane + 96];
        #pragma unroll
        for (int off = 16; off > 0; off >>= 1)
            s += __shfl_xor_sync(0xFFFFFFFFu, s, off);
        if (lane == 0) out[b] = s + __ldg(b3);
    }

    // tail reset for the next graph replay
    if (b == 0 && threadIdx.x == 0) { g_ticket = 0; g_nwork = 0; g_done_cnt = 0; }
}

// ============================================================================
// kernel_launch
// ============================================================================
extern "C" void kernel_launch(void* const* d_in, const int* in_sizes, int n_in,
                              void* d_out, int out_size) {
    const float* x   = (const float*)d_in[0];
    const float* pw0 = (const float*)d_in[1];
    const float* pb0 = (const float*)d_in[2];
    const float* pw1 = (const float*)d_in[3];
    const float* pb1 = (const float*)d_in[4];
    const float* pw2 = (const float*)d_in[5];
    const float* pb2 = (const float*)d_in[6];
    const float* pw3 = (const float*)d_in[7];
    const float* pb3 = (const float*)d_in[8];
    const float* rw0 = (const float*)d_in[9];
    const float* rb0 = (const float*)d_in[10];
    const float* rw1 = (const float*)d_in[11];
    const float* rb1 = (const float*)d_in[12];
    const float* rw2 = (const float*)d_in[13];
    const float* rb2 = (const float*)d_in[14];
    const float* rw3 = (const float*)d_in[15];
    const float* rb3 = (const float*)d_in[16];

    static bool attr_set = false;
    if (!attr_set) {
        cudaFuncSetAttribute(phi_kernel, cudaFuncAttributeMaxDynamicSharedMemorySize, SMEM_TOTAL);
        attr_set = true;
    }

    phi_kernel<<<PHI_GRID, PHI_THREADS, SMEM_TOTAL>>>(x, pw0, pb0, pw1, pb1, pw2, pb2, pw3, pb3);
    rho_kernel<<<BB, 256>>>(rw0, rb0, rw1, rb1, rw2, rb2, rw3, rb3, (float*)d_out);
}